// round 2
// baseline (speedup 1.0000x reference)
#include <cuda_runtime.h>
#include <math.h>

// Problem constants (fixed by reference setup_inputs)
#define B 32
#define D 64
#define H 192
#define W 128
#define K 64

__device__ float g_batch_loss[B];

// One CTA per batch sample. 256 threads.
__global__ __launch_bounds__(256, 1)
void tagloss_batch_kernel(const float* __restrict__ ebd,
                          const float* __restrict__ kpts,
                          const int* __restrict__ tags)
{
    const int b   = blockIdx.x;
    const int tid = threadIdx.x;

    __shared__ float e[K][D + 1];   // padded: bank-conflict-free
    __shared__ int   sr[K], sc[K];
    __shared__ int   stags[K];
    __shared__ float red[256];

    // --- keypoint -> pixel indices + tags ---
    if (tid < K) {
        float r = kpts[((size_t)b * K + tid) * 2 + 0] * (float)H;
        float c = kpts[((size_t)b * K + tid) * 2 + 1] * (float)W;
        sr[tid] = (int)floorf(r);
        sc[tid] = (int)floorf(c);
        stags[tid] = tags[(size_t)b * K + tid];
    }
    __syncthreads();

    // --- gather: e[k][d] = ebd[b, d, r_k, c_k]  (4096 scattered loads) ---
    const float* eb = ebd + (size_t)b * D * H * W;
    #pragma unroll
    for (int n = tid; n < K * D; n += 256) {
        int k = n >> 6;       // keypoint
        int d = n & 63;       // channel
        e[k][d] = eb[(size_t)d * (H * W) + sr[k] * W + sc[k]];
    }
    __syncthreads();

    // --- pairwise loss ---
    // Each thread owns column j = tid & 63; hoist e[j][*] to registers.
    const int j = tid & 63;
    float ej[D];
    #pragma unroll
    for (int d = 0; d < D; d++) ej[d] = e[j][d];
    const int tj = stags[j];

    float acc = 0.0f;
    #pragma unroll 1
    for (int ig = 0; ig < 16; ig++) {
        const int i = (tid >> 6) + ig * 4;
        float s = 0.0f;
        #pragma unroll
        for (int d = 0; d < D; d++) {
            float df = e[i][d] - ej[d];
            s = fmaf(df, df, s);
        }
        float expo = s * (1.0f / (float)D);
        float pred = 2.0f / (1.0f + expf(expo));
        float ts   = (stags[i] == tj) ? 1.0f : 0.0f;
        float dd   = pred - ts;
        acc = fmaf(dd, dd, acc);
    }

    // --- block reduction of 256 partials ---
    red[tid] = acc;
    __syncthreads();
    for (int off = 128; off >= 32; off >>= 1) {
        if (tid < off) red[tid] += red[tid + off];
        __syncthreads();
    }
    if (tid < 32) {
        float v = red[tid];
        #pragma unroll
        for (int o = 16; o > 0; o >>= 1)
            v += __shfl_down_sync(0xFFFFFFFFu, v, o);
        if (tid == 0)
            g_batch_loss[b] = v * (1.0f / (float)(K * K));
    }
}

// Final reduce: mean over the 32 per-batch losses.
__global__ void tagloss_final_kernel(float* __restrict__ out)
{
    const int tid = threadIdx.x;   // 32 threads
    float v = g_batch_loss[tid];
    #pragma unroll
    for (int o = 16; o > 0; o >>= 1)
        v += __shfl_down_sync(0xFFFFFFFFu, v, o);
    if (tid == 0) out[0] = v * (1.0f / (float)B);
}

extern "C" void kernel_launch(void* const* d_in, const int* in_sizes, int n_in,
                              void* d_out, int out_size)
{
    const float* ebd  = (const float*)d_in[0];   // [32,64,192,128] f32
    const float* kpts = (const float*)d_in[1];   // [32,64,2] f32
    const int*   tags = (const int*)d_in[2];     // [32,64] i32 (JAX x64-off downcast)
    float* out = (float*)d_out;

    tagloss_batch_kernel<<<B, 256>>>(ebd, kpts, tags);
    tagloss_final_kernel<<<1, 32>>>(out);
}

// round 3
// speedup vs baseline: 1.5552x; 1.5552x over previous
#include <cuda_runtime.h>
#include <math.h>

// Problem constants (fixed by reference setup_inputs)
#define B 32
#define D 64
#define H 192
#define W 128
#define K 64
#define CPB 4                 // CTAs per batch sample
#define GRID (B * CPB)        // 128
#define IPC (K / CPB)         // 16 i-rows per CTA
#define THREADS 256

__device__ float        g_partial[GRID];
__device__ unsigned int g_count = 0;

__global__ __launch_bounds__(THREADS, 1)
void tagloss_fused_kernel(const float* __restrict__ ebd,
                          const float* __restrict__ kpts,
                          const int*   __restrict__ tags,
                          float*       __restrict__ out)
{
    const int cta   = blockIdx.x;
    const int b     = cta >> 2;        // batch sample
    const int chunk = cta & 3;         // which 16 i-rows
    const int tid   = threadIdx.x;

    __shared__ float eT[D][K];         // [d][k]: conflict-free column reads
    __shared__ float erow[K][D + 4];   // [k][d]: 16B-aligned rows for LDS.128 broadcast
    __shared__ float snorm[K];
    __shared__ int   sr[K], sc[K], stags[K];
    __shared__ float red[THREADS];
    __shared__ bool  s_last;

    // --- keypoint -> pixel indices + tags ---
    if (tid < K) {
        float r = kpts[((size_t)b * K + tid) * 2 + 0] * (float)H;
        float c = kpts[((size_t)b * K + tid) * 2 + 1] * (float)W;
        sr[tid] = (int)floorf(r);
        sc[tid] = (int)floorf(c);
        stags[tid] = tags[(size_t)b * K + tid];
    }
    __syncthreads();

    // --- gather: 4096 scattered loads; lanes take consecutive k (conflict-free STS) ---
    const float* eb = ebd + (size_t)b * D * H * W;
    #pragma unroll
    for (int it = 0; it < (K * D) / THREADS; it++) {
        int n = tid + it * THREADS;
        int k = n & 63;
        int d = n >> 6;
        float v = eb[(size_t)d * (H * W) + sr[k] * W + sc[k]];
        eT[d][k]   = v;
        erow[k][d] = v;
    }
    __syncthreads();

    // --- per-keypoint squared norms (sequential FFMA order; matches self-dot exactly) ---
    if (tid < K) {
        float s = 0.0f;
        #pragma unroll
        for (int d = 0; d < D; d++) s = fmaf(eT[d][tid], eT[d][tid], s);
        snorm[tid] = s;
    }
    __syncthreads();

    // --- pairwise loss: thread owns column j; hoist e_j into registers ---
    const int j = tid & 63;
    float ej[D];
    #pragma unroll
    for (int d = 0; d < D; d++) ej[d] = eT[d][j];
    const float nj = snorm[j];
    const int   tj = stags[j];

    const int i0 = chunk * IPC + (tid >> 6);   // this CTA's i-rows, step 4
    float acc = 0.0f;
    #pragma unroll
    for (int ig = 0; ig < IPC / 4; ig++) {     // 4 iterations
        const int i = i0 + ig * 4;
        const float4* rowi = (const float4*)erow[i];
        float s = 0.0f;
        #pragma unroll
        for (int d4 = 0; d4 < D / 4; d4++) {   // LDS.128 broadcast
            float4 v = rowi[d4];
            s = fmaf(v.x, ej[d4 * 4 + 0], s);
            s = fmaf(v.y, ej[d4 * 4 + 1], s);
            s = fmaf(v.z, ej[d4 * 4 + 2], s);
            s = fmaf(v.w, ej[d4 * 4 + 3], s);
        }
        float expo = (snorm[i] + nj - 2.0f * s) * (1.0f / (float)D);
        float pred = 2.0f / (1.0f + __expf(expo));
        float ts   = (stags[i] == tj) ? 1.0f : 0.0f;
        float dd   = pred - ts;
        acc = fmaf(dd, dd, acc);
    }

    // --- CTA reduction of 256 partials ---
    red[tid] = acc;
    __syncthreads();
    #pragma unroll
    for (int off = 128; off >= 32; off >>= 1) {
        if (tid < off) red[tid] += red[tid + off];
        __syncthreads();
    }
    if (tid < 32) {
        float v = red[tid];
        #pragma unroll
        for (int o = 16; o > 0; o >>= 1)
            v += __shfl_down_sync(0xFFFFFFFFu, v, o);
        if (tid == 0) {
            g_partial[cta] = v;
            __threadfence();
            unsigned old = atomicAdd(&g_count, 1u);
            s_last = (old == GRID - 1);
        }
    }
    __syncthreads();

    // --- last CTA: deterministic final reduce over 128 partials ---
    if (s_last && tid < 32) {
        float v = g_partial[tid]      + g_partial[tid + 32]
                + g_partial[tid + 64] + g_partial[tid + 96];
        #pragma unroll
        for (int o = 16; o > 0; o >>= 1)
            v += __shfl_down_sync(0xFFFFFFFFu, v, o);
        if (tid == 0) {
            out[0] = v * (1.0f / (float)(K * K * B));
            g_count = 0;                 // reset for next graph replay
        }
    }
}

extern "C" void kernel_launch(void* const* d_in, const int* in_sizes, int n_in,
                              void* d_out, int out_size)
{
    const float* ebd  = (const float*)d_in[0];   // [32,64,192,128] f32
    const float* kpts = (const float*)d_in[1];   // [32,64,2] f32
    const int*   tags = (const int*)d_in[2];     // [32,64] i32
    float* out = (float*)d_out;

    tagloss_fused_kernel<<<GRID, THREADS>>>(ebd, kpts, tags, out);
}